// round 9
// baseline (speedup 1.0000x reference)
#include <cuda_runtime.h>
#include <math.h>
#include <stdint.h>

// Problem shapes (fixed for this bench)
#define BB 4
#define TT 512
#define SS 1024
#define HH 768
#define VV 50257

// FOUR CTAs per (b,t) row; q = blockIdx>>11 so quarter-0 CTAs are blocks
// 0..2047 (scheduled first -> producer/consumer windows stay within ~1 wave).
#define VPADQ  12568                 // pad(<=3) + max quarter (12565), rounded
#define SMEM_FLOATS (VPADQ + 32)
#define SMEM_BYTES  (SMEM_FLOATS * 4)
#define NTHR 512
#define ROWS_PER_B 512               // rows (=producer CTAs) per batch

// Collapsed p_gen projection u[b,s] = src[b,s,:].W[:H]; produced in-kernel.
__device__ float g_u[BB * SS];
// Per-batch handshake counters (must return to 0 each launch for graph replay).
__device__ int g_cnt[BB];            // producers done for batch b
__device__ int g_used[BB];           // consumers done for batch b

// ---------------------------------------------------------------------------
// Single fused kernel. Four CTAs per (b,t) row, each owning a vocab quarter.
//   Quarter-0 CTAs additionally produce u[b,2r], u[b,2r+1] and local v[row]
//   (warps 0-2) while the other warps start zeroing; consume the full u[b,:]
//   after issuing their TMA drain (spin overlapped with the drain).
// ---------------------------------------------------------------------------
__global__ __launch_bounds__(NTHR, 4)
void copy_logits_kernel(const int* __restrict__ ids,
                        const float* __restrict__ attn,
                        const float* __restrict__ src,
                        const float* __restrict__ tgt,
                        const float* __restrict__ W,
                        const float* __restrict__ bias,
                        float* __restrict__ out_pgen,
                        float* __restrict__ out_logits)
{
    extern __shared__ float sm[];  // [VPADQ] accum | [16] red | [3] u0,u1,v
    const int row = blockIdx.x & 2047;     // b*T + t
    const int q   = blockIdx.x >> 11;
    const int b   = row >> 9;              // row / TT
    const int tid = threadIdx.x;
    const int wid = tid >> 5;
    const int lane = tid & 31;

    float* red  = sm + VPADQ;              // [16]
    float* prod = sm + VPADQ + 16;         // [0]=u(2r) [1]=u(2r+1) [2]=v

    const int lo = (q * VV) >> 2;
    const int hi = ((q + 1) * VV) >> 2;
    const int n  = hi - lo;

    // Producer phase (quarter-0 CTAs, warps 0-2) — runs while warps 3+ zero.
    if (q == 0 && wid < 3) {
        const int r = row & (ROWS_PER_B - 1);
        const float4* x;
        const float4* w;
        if (wid < 2) {                     // u[b, 2r+wid]
            x = reinterpret_cast<const float4*>(src + ((size_t)b * SS + 2 * r + wid) * HH);
            w = reinterpret_cast<const float4*>(W);
        } else {                           // v[row]
            x = reinterpret_cast<const float4*>(tgt + (size_t)row * HH);
            w = reinterpret_cast<const float4*>(W + HH);
        }
        float acc = 0.f;
        #pragma unroll
        for (int j = lane; j < HH / 4; j += 32) {
            float4 aa = x[j], bb = w[j];
            acc += aa.x * bb.x + aa.y * bb.y + aa.z * bb.z + aa.w * bb.w;
        }
        #pragma unroll
        for (int o = 16; o; o >>= 1) acc += __shfl_xor_sync(0xffffffffu, acc, o);
        if (lane == 0) prod[wid] = (wid == 2) ? acc + bias[0] : acc;
    }

    // Global destination of this quarter-row; 16B phase decides head & pad.
    float* dst = out_logits + (size_t)row * VV + lo;
    const int head = (int)(((16u - ((uint32_t)(uintptr_t)dst & 15u)) & 15u) >> 2);
    const int pad  = (4 - head) & 3;       // sm[pad+head] is 16B-aligned

    // Phase 1: zero the accumulator (vectorized STS.128), all warps.
    float4* sm4 = reinterpret_cast<float4*>(sm);
    const float4 z4 = make_float4(0.f, 0.f, 0.f, 0.f);
    #pragma unroll
    for (int i = tid; i < VPADQ / 4; i += NTHR) sm4[i] = z4;
    __syncthreads();                       // zero done; producer dots in smem

    // Publish u-values (thread 0 = writer+fencer+signaler: release pattern).
    if (q == 0 && tid == 0) {
        const int r = row & (ROWS_PER_B - 1);
        g_u[b * SS + 2 * r]     = prod[0];
        g_u[b * SS + 2 * r + 1] = prod[1];
        __threadfence();
        atomicAdd(&g_cnt[b], 1);
    }

    // Phase 2: range-predicated scatter-add; each thread covers 2 positions.
    const float a0  = attn[(size_t)row * SS + tid];
    const float a1  = attn[(size_t)row * SS + tid + NTHR];
    const int   id0 = ids[b * SS + tid];
    const int   id1 = ids[b * SS + tid + NTHR];
    if (id0 >= lo && id0 < hi) atomicAdd(&sm[pad + id0 - lo], a0);
    if (id1 >= lo && id1 < hi) atomicAdd(&sm[pad + id1 - lo], a1);
    __syncthreads();                       // all atomics complete

    // Phase 3: head/tail scalars + one bulk-async (TMA) copy for the middle.
    const int nvec = (n - head) >> 2;
    const int tail = head + 4 * nvec;

    if (tid < head)     __stcs(dst + tid, sm[pad + tid]);
    if (tid < n - tail) __stcs(dst + tail + tid, sm[pad + tail + tid]);

    if (tid == 0) {
        asm volatile("fence.proxy.async.shared::cta;" ::: "memory");
        uint32_t saddr;
        asm("{ .reg .u64 t; cvta.to.shared.u64 t, %1; cvt.u32.u64 %0, t; }"
            : "=r"(saddr) : "l"(sm + pad + head));
        asm volatile(
            "cp.async.bulk.global.shared::cta.bulk_group [%0], [%1], %2;"
            :: "l"(dst + head), "r"(saddr), "r"(16 * nvec) : "memory");
        asm volatile("cp.async.bulk.commit_group;" ::: "memory");
    }

    // Phase 4 (quarter-0): wait for this batch's 512 producers (overlapped
    // with our own TMA drain), then fused p_gen = sigmoid(attn.u + v).
    if (q == 0) {
        if (tid == 0) {
            int c;
            do {
                asm volatile("ld.global.acquire.gpu.b32 %0, [%1];"
                             : "=r"(c) : "l"(&g_cnt[b]) : "memory");
                if (c < ROWS_PER_B) __nanosleep(64);
            } while (c < ROWS_PER_B);
        }
        __syncthreads();                   // all threads: u is ready

        float part = a0 * __ldcg(&g_u[b * SS + tid])
                   + a1 * __ldcg(&g_u[b * SS + tid + NTHR]);
        #pragma unroll
        for (int o = 16; o; o >>= 1) part += __shfl_xor_sync(0xffffffffu, part, o);
        if ((tid & 31) == 0) red[tid >> 5] = part;
        __syncthreads();
        if (tid == 0) {
            float x = 0.f;
            #pragma unroll
            for (int i = 0; i < 16; i++) x += red[i];
            const float zv = x + prod[2];
            out_pgen[row] = 1.f / (1.f + __expf(-zv));
            // Handshake: last consumer of batch b resets counters (so every
            // graph replay starts from g_cnt=g_used=0 -> deterministic).
            if (atomicAdd(&g_used[b], 1) == ROWS_PER_B - 1) {
                g_cnt[b]  = 0;
                g_used[b] = 0;
            }
        }
    }

    if (tid == 0)
        asm volatile("cp.async.bulk.wait_group 0;" ::: "memory");
}

// ---------------------------------------------------------------------------
// Launch: ONE kernel, no prep, no PDL.
// ---------------------------------------------------------------------------
extern "C" void kernel_launch(void* const* d_in, const int* in_sizes, int n_in,
                              void* d_out, int out_size)
{
    const int*   ids  = (const int*)  d_in[0];  // [B,S] int32
    const float* attn = (const float*)d_in[1];  // [B,T,S]
    const float* src  = (const float*)d_in[2];  // [B,S,H]
    const float* tgt  = (const float*)d_in[3];  // [B,T,H]
    const float* W    = (const float*)d_in[4];  // [2H,1]
    const float* bias = (const float*)d_in[5];  // [1]

    float* out_pgen   = (float*)d_out;              // [B,T]  (first output)
    float* out_logits = out_pgen + (size_t)BB * TT; // [B,T,V]

    cudaFuncSetAttribute(copy_logits_kernel,
                         cudaFuncAttributeMaxDynamicSharedMemorySize,
                         SMEM_BYTES);

    copy_logits_kernel<<<BB * TT * 4, NTHR, SMEM_BYTES>>>(
        ids, attn, src, tgt, W, bias, out_pgen, out_logits);
}

// round 10
// speedup vs baseline: 1.1375x; 1.1375x over previous
#include <cuda_runtime.h>
#include <math.h>
#include <stdint.h>

// Problem shapes (fixed for this bench)
#define BB 4
#define TT 512
#define SS 1024
#define HH 768
#define VV 50257

// Copy role: FOUR CTAs per (b,t) row, each owning a vocab quarter.
#define VPADQ  12568                 // pad(<=3) + max quarter (12565), rounded
#define SMEM_FLOATS (VPADQ + 16)
#define SMEM_BYTES  (SMEM_FLOATS * 4)
#define NTHR 512

// Pgen cohort: first NPGEN blocks (guaranteed co-resident in wave 1).
#define NPGEN 148
#define PGEN_WARPS (NPGEN * (NTHR / 32))   // 2368 warps
#define NROWS (BB * TT)                    // 2048
#define NU    (BB * SS)                    // 4096 u rows
#define NUV   (NU + NROWS)                 // 6144 projection rows

// Collapsed p_gen projections, produced and consumed inside the cohort.
__device__ float g_u[NU];
__device__ float g_v[NROWS];
__device__ int   g_cnt;     // cohort barrier arrivals (returns to 0 each launch)
__device__ int   g_done;    // cohort exit count       (returns to 0 each launch)

// ---------------------------------------------------------------------------
// Single launch, two roles.
//  Blocks 0..147   : pgen cohort — compute u,v; 148-CTA device barrier;
//                    then p_gen[row] = sigmoid(attn[row,:].u[b,:] + v[row]).
//  Blocks 148..4243: pure copy CTAs (R8 shape): zero smem accumulator,
//                    shared-atomic scatter, one TMA bulk-store per quarter-row.
// ---------------------------------------------------------------------------
__global__ __launch_bounds__(NTHR, 4)
void copy_logits_kernel(const int* __restrict__ ids,
                        const float* __restrict__ attn,
                        const float* __restrict__ src,
                        const float* __restrict__ tgt,
                        const float* __restrict__ W,
                        const float* __restrict__ bias,
                        float* __restrict__ out_pgen,
                        float* __restrict__ out_logits)
{
    extern __shared__ float sm[];
    const int tid  = threadIdx.x;
    const int wid  = tid >> 5;
    const int lane = tid & 31;

    if (blockIdx.x < NPGEN) {
        // ----------------- pgen cohort -----------------
        const int gw = blockIdx.x * (NTHR / 32) + wid;   // 0..2367

        // Phase A: projections. Row rr<NU: u[rr]=src[rr,:].W1; else v row.
        for (int rr = gw; rr < NUV; rr += PGEN_WARPS) {
            const float4* x;
            const float4* w;
            if (rr < NU) {
                x = reinterpret_cast<const float4*>(src + (size_t)rr * HH);
                w = reinterpret_cast<const float4*>(W);
            } else {
                x = reinterpret_cast<const float4*>(tgt + (size_t)(rr - NU) * HH);
                w = reinterpret_cast<const float4*>(W + HH);
            }
            float acc = 0.f;
            #pragma unroll
            for (int j = lane; j < HH / 4; j += 32) {
                float4 aa = x[j], bb = w[j];
                acc += aa.x * bb.x + aa.y * bb.y + aa.z * bb.z + aa.w * bb.w;
            }
            #pragma unroll
            for (int o = 16; o; o >>= 1) acc += __shfl_xor_sync(0xffffffffu, acc, o);
            if (lane == 0) {
                if (rr < NU) g_u[rr] = acc;
                else         g_v[rr - NU] = acc + bias[0];
            }
        }

        // Cohort barrier (release: block's writes -> fence -> arrive).
        __syncthreads();
        if (tid == 0) {
            __threadfence();
            atomicAdd(&g_cnt, 1);
            int c;
            do {
                asm volatile("ld.global.acquire.gpu.b32 %0, [%1];"
                             : "=r"(c) : "l"(&g_cnt) : "memory");
                if (c < NPGEN) __nanosleep(100);
            } while (c < NPGEN);
        }
        __syncthreads();   // all threads: full u,v visible

        // Phase B: p_gen rows (one warp per row; 2368 warps >= 2048 rows).
        if (gw < NROWS) {
            const int row = gw;
            const int b   = row >> 9;
            const float4* ar = reinterpret_cast<const float4*>(attn + (size_t)row * SS);
            const float4* ur = reinterpret_cast<const float4*>(g_u + b * SS);
            float acc = 0.f;
            #pragma unroll
            for (int j = lane; j < SS / 4; j += 32) {
                float4 aa = ar[j], uu = ur[j];
                acc += aa.x * uu.x + aa.y * uu.y + aa.z * uu.z + aa.w * uu.w;
            }
            #pragma unroll
            for (int o = 16; o; o >>= 1) acc += __shfl_xor_sync(0xffffffffu, acc, o);
            if (lane == 0) {
                const float zv = acc + g_v[row];
                out_pgen[row] = 1.f / (1.f + __expf(-zv));
            }
        }

        // Reset counters for the next graph replay (deterministic state).
        __syncthreads();
        if (tid == 0) {
            if (atomicAdd(&g_done, 1) == NPGEN - 1) {
                g_cnt  = 0;
                g_done = 0;
            }
        }
        return;
    }

    // ----------------- copy role (pure, R8 shape) -----------------
    const int cid = blockIdx.x - NPGEN;    // 0..4095
    const int row = cid & 2047;            // b*T + t
    const int q   = cid >> 11;             // vocab quarter
    const int b   = row >> 9;

    const int lo = (q * VV) >> 2;
    const int hi = ((q + 1) * VV) >> 2;
    const int n  = hi - lo;

    // Global destination of this quarter-row; 16B phase decides head & pad.
    float* dst = out_logits + (size_t)row * VV + lo;
    const int head = (int)(((16u - ((uint32_t)(uintptr_t)dst & 15u)) & 15u) >> 2);
    const int pad  = (4 - head) & 3;       // sm[pad+head] is 16B-aligned

    // Phase 1: zero the accumulator (vectorized STS.128).
    float4* sm4 = reinterpret_cast<float4*>(sm);
    const float4 z4 = make_float4(0.f, 0.f, 0.f, 0.f);
    #pragma unroll
    for (int i = tid; i < VPADQ / 4; i += NTHR) sm4[i] = z4;
    __syncthreads();

    // Phase 2: range-predicated scatter-add; each thread covers 2 positions.
    const float a0  = attn[(size_t)row * SS + tid];
    const float a1  = attn[(size_t)row * SS + tid + NTHR];
    const int   id0 = ids[b * SS + tid];
    const int   id1 = ids[b * SS + tid + NTHR];
    if (id0 >= lo && id0 < hi) atomicAdd(&sm[pad + id0 - lo], a0);
    if (id1 >= lo && id1 < hi) atomicAdd(&sm[pad + id1 - lo], a1);
    __syncthreads();   // all atomics complete

    // Phase 3: head/tail scalars + one bulk-async (TMA) copy for the middle.
    const int nvec = (n - head) >> 2;
    const int tail = head + 4 * nvec;

    if (tid < head)     __stcs(dst + tid, sm[pad + tid]);
    if (tid < n - tail) __stcs(dst + tail + tid, sm[pad + tail + tid]);

    if (tid == 0) {
        asm volatile("fence.proxy.async.shared::cta;" ::: "memory");
        uint32_t saddr;
        asm("{ .reg .u64 t; cvta.to.shared.u64 t, %1; cvt.u32.u64 %0, t; }"
            : "=r"(saddr) : "l"(sm + pad + head));
        asm volatile(
            "cp.async.bulk.global.shared::cta.bulk_group [%0], [%1], %2;"
            :: "l"(dst + head), "r"(saddr), "r"(16 * nvec) : "memory");
        asm volatile("cp.async.bulk.commit_group;" ::: "memory");
        asm volatile("cp.async.bulk.wait_group 0;" ::: "memory");
    }
}

// ---------------------------------------------------------------------------
// Launch: ONE kernel.
// ---------------------------------------------------------------------------
extern "C" void kernel_launch(void* const* d_in, const int* in_sizes, int n_in,
                              void* d_out, int out_size)
{
    const int*   ids  = (const int*)  d_in[0];  // [B,S] int32
    const float* attn = (const float*)d_in[1];  // [B,T,S]
    const float* src  = (const float*)d_in[2];  // [B,S,H]
    const float* tgt  = (const float*)d_in[3];  // [B,T,H]
    const float* W    = (const float*)d_in[4];  // [2H,1]
    const float* bias = (const float*)d_in[5];  // [1]

    float* out_pgen   = (float*)d_out;              // [B,T]  (first output)
    float* out_logits = out_pgen + (size_t)BB * TT; // [B,T,V]

    cudaFuncSetAttribute(copy_logits_kernel,
                         cudaFuncAttributeMaxDynamicSharedMemorySize,
                         SMEM_BYTES);

    copy_logits_kernel<<<NPGEN + BB * TT * 4, NTHR, SMEM_BYTES>>>(
        ids, attn, src, tgt, W, bias, out_pgen, out_logits);
}

// round 11
// speedup vs baseline: 1.1760x; 1.0339x over previous
#include <cuda_runtime.h>
#include <math.h>
#include <stdint.h>

// Problem shapes (fixed for this bench)
#define BB 4
#define TT 512
#define SS 1024
#define HH 768
#define VV 50257

// Copy role: TWO CTAs per (b,t) row (R6 shape — fastest measured copy).
#define VLO1   25129                 // half0 = [0,25129), half1 = [25129,50257)
#define VPADH  25136                 // pad(<=3) + 25129, rounded up
#define SMEM_FLOATS (VPADH + 32)
#define SMEM_BYTES  (SMEM_FLOATS * 4)
#define NTHR 1024

// Pgen cohort: first NPGEN blocks (co-resident in wave 1), Phase A only.
#define NPGEN 148
#define COHORT_WARPS (NPGEN * 32)    // 4736
#define NROWS (BB * TT)              // 2048
#define NU    (BB * SS)              // 4096 u rows
#define NUV   (NU + NROWS)           // 6144 projection rows

// Collapsed p_gen projections (produced by cohort, consumed by half-0 CTAs).
__device__ float g_u[NU];
__device__ float g_v[NROWS];
__device__ int   g_cnt;     // cohort arrivals; reset each launch by consumers
__device__ int   g_used;    // consumer exits; reset each launch

// ---------------------------------------------------------------------------
// Single launch, two roles.
//  Blocks 0..147  : cohort — compute u,v (19MB reads), release g_cnt, EXIT.
//  Blocks 148+    : copy CTAs (2 per row, ~100KB smem): zero accumulator,
//                   shared-atomic scatter, one TMA bulk-store; half-0 CTAs
//                   additionally compute p_gen after issuing the TMA drain
//                   (poll overlapped with the drain; 1us backoff).
// ---------------------------------------------------------------------------
__global__ __launch_bounds__(NTHR, 2)
void copy_logits_kernel(const int* __restrict__ ids,
                        const float* __restrict__ attn,
                        const float* __restrict__ src,
                        const float* __restrict__ tgt,
                        const float* __restrict__ W,
                        const float* __restrict__ bias,
                        float* __restrict__ out_pgen,
                        float* __restrict__ out_logits)
{
    extern __shared__ float sm[];          // [VPADH] accum | [32] reduce
    const int tid  = threadIdx.x;
    const int wid  = tid >> 5;
    const int lane = tid & 31;

    if (blockIdx.x < NPGEN) {
        // ----------------- cohort: projections only, then exit ------------
        for (int rr = blockIdx.x * 32 + wid; rr < NUV; rr += COHORT_WARPS) {
            const float4* x;
            const float4* w;
            if (rr < NU) {
                x = reinterpret_cast<const float4*>(src + (size_t)rr * HH);
                w = reinterpret_cast<const float4*>(W);
            } else {
                x = reinterpret_cast<const float4*>(tgt + (size_t)(rr - NU) * HH);
                w = reinterpret_cast<const float4*>(W + HH);
            }
            float acc = 0.f;
            #pragma unroll
            for (int j = lane; j < HH / 4; j += 32) {
                float4 aa = x[j], bb = w[j];
                acc += aa.x * bb.x + aa.y * bb.y + aa.z * bb.z + aa.w * bb.w;
            }
            #pragma unroll
            for (int o = 16; o; o >>= 1) acc += __shfl_xor_sync(0xffffffffu, acc, o);
            if (lane == 0) {
                if (rr < NU) g_u[rr] = acc;
                else         g_v[rr - NU] = acc + bias[0];
            }
        }
        __syncthreads();
        if (tid == 0) {                    // release: writes -> fence -> count
            __threadfence();
            atomicAdd(&g_cnt, 1);
        }
        return;                            // slot freed immediately
    }

    // ----------------- copy role (R6 2-way shape) -------------------------
    const int cid  = blockIdx.x - NPGEN;   // 0..4095
    const int row  = cid >> 1;             // b*T + t
    const int half = cid & 1;
    const int b    = row >> 9;

    const int lo = half ? VLO1 : 0;
    const int hi = half ? VV   : VLO1;
    const int n  = hi - lo;

    // Global destination of this half-row; 16B phase decides head & pad.
    float* dst = out_logits + (size_t)row * VV + lo;
    const int head = (int)(((16u - ((uint32_t)(uintptr_t)dst & 15u)) & 15u) >> 2);
    const int pad  = (4 - head) & 3;       // sm[pad+head] is 16B-aligned

    // Phase 1: zero the accumulator (vectorized STS.128).
    float4* sm4 = reinterpret_cast<float4*>(sm);
    const float4 z4 = make_float4(0.f, 0.f, 0.f, 0.f);
    #pragma unroll
    for (int i = tid; i < VPADH / 4; i += NTHR) sm4[i] = z4;
    __syncthreads();

    // Phase 2: range-predicated scatter-add. Exactly S=1024 threads, 1 each.
    const float a  = attn[(size_t)row * SS + tid];
    const int   id = ids[b * SS + tid];
    if (id >= lo && id < hi) atomicAdd(&sm[pad + id - lo], a);
    __syncthreads();                       // all atomics complete

    // Phase 3: head/tail scalars + one bulk-async (TMA) copy for the middle.
    const int nvec = (n - head) >> 2;
    const int tail = head + 4 * nvec;

    if (tid < head)     __stcs(dst + tid, sm[pad + tid]);
    if (tid < n - tail) __stcs(dst + tail + tid, sm[pad + tail + tid]);

    if (tid == 0) {
        asm volatile("fence.proxy.async.shared::cta;" ::: "memory");
        uint32_t saddr;
        asm("{ .reg .u64 t; cvta.to.shared.u64 t, %1; cvt.u32.u64 %0, t; }"
            : "=r"(saddr) : "l"(sm + pad + head));
        asm volatile(
            "cp.async.bulk.global.shared::cta.bulk_group [%0], [%1], %2;"
            :: "l"(dst + head), "r"(saddr), "r"(16 * nvec) : "memory");
        asm volatile("cp.async.bulk.commit_group;" ::: "memory");
    }

    // Phase 4 (half-0): wait for cohort (overlapped with our own TMA drain,
    // gentle 1us backoff), then fused p_gen = sigmoid(attn.u + v).
    if (half == 0) {
        if (tid == 0) {
            int c;
            do {
                asm volatile("ld.global.acquire.gpu.b32 %0, [%1];"
                             : "=r"(c) : "l"(&g_cnt) : "memory");
                if (c < NPGEN) __nanosleep(1000);
            } while (c < NPGEN);
        }
        __syncthreads();                   // all threads: u,v visible

        float part = a * __ldcg(&g_u[b * SS + tid]);
        #pragma unroll
        for (int o = 16; o; o >>= 1) part += __shfl_xor_sync(0xffffffffu, part, o);
        float* red = sm + VPADH;
        if ((tid & 31) == 0) red[tid >> 5] = part;
        __syncthreads();
        if (tid == 0) {
            float x = 0.f;
            #pragma unroll
            for (int i = 0; i < 32; i++) x += red[i];
            const float zv = x + g_v[row];
            out_pgen[row] = 1.f / (1.f + __expf(-zv));
            // Last consumer resets counters -> deterministic graph replays.
            if (atomicAdd(&g_used, 1) == NROWS - 1) {
                g_cnt  = 0;
                g_used = 0;
            }
        }
    }

    if (tid == 0)
        asm volatile("cp.async.bulk.wait_group 0;" ::: "memory");
}

// ---------------------------------------------------------------------------
// Launch: ONE kernel.
// ---------------------------------------------------------------------------
extern "C" void kernel_launch(void* const* d_in, const int* in_sizes, int n_in,
                              void* d_out, int out_size)
{
    const int*   ids  = (const int*)  d_in[0];  // [B,S] int32
    const float* attn = (const float*)d_in[1];  // [B,T,S]
    const float* src  = (const float*)d_in[2];  // [B,S,H]
    const float* tgt  = (const float*)d_in[3];  // [B,T,H]
    const float* W    = (const float*)d_in[4];  // [2H,1]
    const float* bias = (const float*)d_in[5];  // [1]

    float* out_pgen   = (float*)d_out;              // [B,T]  (first output)
    float* out_logits = out_pgen + (size_t)BB * TT; // [B,T,V]

    cudaFuncSetAttribute(copy_logits_kernel,
                         cudaFuncAttributeMaxDynamicSharedMemorySize,
                         SMEM_BYTES);

    copy_logits_kernel<<<NPGEN + BB * TT * 2, NTHR, SMEM_BYTES>>>(
        ids, attn, src, tgt, W, bias, out_pgen, out_logits);
}